// round 16
// baseline (speedup 1.0000x reference)
#include <cuda_runtime.h>
#include <math.h>
#include <stdint.h>

// ---------------- problem constants ----------------
#define BATCH    4
#define SEQLEN   2048
#define D_MODEL  1024
#define D_STATE  64
#define D_CONV   4
#define HEADDIM  64
#define D_INNER  2048
#define NHEADS   32
#define CONV_DIM 2176          // D_INNER + 2*D_STATE
#define D_IN_PROJ 4256         // 2*D_INNER + 2*D_STATE + NHEADS
#define NROWS    (BATCH * SEQLEN)   // 8192

// ---------------- scratch (static device globals: no allocs allowed) ----------------
__device__ float g_zxbcdt[(size_t)NROWS * D_IN_PROJ];   // 139.5 MB
__device__ float g_xh[(size_t)NROWS * D_INNER];         // 67 MB (post conv+silu)
__device__ float g_Bm[NROWS * D_STATE];
__device__ float g_Cm[NROWS * D_STATE];
__device__ float2 g_dtA[NROWS * NHEADS];                // (dt_softplus, exp(dt*A))
__device__ float g_yscan[(size_t)NROWS * D_INNER];
__device__ float g_y[(size_t)NROWS * D_INNER];          // gated+normed, tf32-rounded
__device__ float g_xr[(size_t)NROWS * D_MODEL];         // x rounded to tf32
__device__ float g_w1r[(size_t)D_MODEL * D_IN_PROJ];    // W_in rounded
__device__ float g_w2r[(size_t)D_INNER * D_MODEL];      // W_out rounded

// ---------------- helpers ----------------
__device__ __forceinline__ float to_tf32(float x) {
    uint32_t u;
    asm("cvt.rna.tf32.f32 %0, %1;" : "=r"(u) : "f"(x));
    return __uint_as_float(u);
}
__device__ __forceinline__ uint32_t smem_u32(const void* p) {
    uint32_t a;
    asm("{ .reg .u64 t; cvta.to.shared.u64 t, %1; cvt.u32.u64 %0, t; }" : "=r"(a) : "l"(p));
    return a;
}
__device__ __forceinline__ void mma_tf32(float* d, const uint32_t* a, const uint32_t* b) {
    asm volatile(
        "mma.sync.aligned.m16n8k8.row.col.f32.tf32.tf32.f32 "
        "{%0,%1,%2,%3}, {%4,%5,%6,%7}, {%8,%9}, {%0,%1,%2,%3};\n"
        : "+f"(d[0]), "+f"(d[1]), "+f"(d[2]), "+f"(d[3])
        : "r"(a[0]), "r"(a[1]), "r"(a[2]), "r"(a[3]), "r"(b[0]), "r"(b[1]));
}
__device__ __forceinline__ void cp16(uint32_t dst, const float* src) {
    asm volatile("cp.async.cg.shared.global [%0], [%1], 16;" :: "r"(dst), "l"(src));
}
__device__ __forceinline__ void cp16z(uint32_t dst, const float* src, int vsz) {
    asm volatile("cp.async.cg.shared.global [%0], [%1], 16, %2;" :: "r"(dst), "l"(src), "r"(vsz));
}
__device__ __forceinline__ void cp8(uint32_t dst, const void* src) {
    asm volatile("cp.async.ca.shared.global [%0], [%1], 8;" :: "r"(dst), "l"(src));
}
#define CP_COMMIT() asm volatile("cp.async.commit_group;" ::: "memory")
#define CP_WAIT1()  asm volatile("cp.async.wait_group 1;" ::: "memory")
#define CP_WAIT5()  asm volatile("cp.async.wait_group 5;" ::: "memory")

// packed f32x2 ops (Blackwell base ISA)
__device__ __forceinline__ unsigned long long fma2_(unsigned long long a, unsigned long long b,
                                                    unsigned long long c) {
    unsigned long long d;
    asm("fma.rn.f32x2 %0, %1, %2, %3;" : "=l"(d) : "l"(a), "l"(b), "l"(c));
    return d;
}
__device__ __forceinline__ unsigned long long mul2_(unsigned long long a, unsigned long long b) {
    unsigned long long d;
    asm("mul.rn.f32x2 %0, %1, %2;" : "=l"(d) : "l"(a), "l"(b));
    return d;
}
__device__ __forceinline__ unsigned long long pack2_(float lo, float hi) {
    unsigned long long d;
    asm("mov.b64 %0, {%1, %2};" : "=l"(d) : "f"(lo), "f"(hi));
    return d;
}
__device__ __forceinline__ float2 unpack2_(unsigned long long v) {
    float lo, hi;
    asm("mov.b64 {%0, %1}, %2;" : "=f"(lo), "=f"(hi) : "l"(v));
    return make_float2(lo, hi);
}

// round fp32 -> tf32-in-fp32
__global__ __launch_bounds__(256)
void round_tf32_kernel(const float* __restrict__ src, float* __restrict__ dst, size_t n4) {
    const size_t i = (size_t)blockIdx.x * 256 + threadIdx.x;
    if (i < n4) {
        float4 v = ((const float4*)src)[i];
        v.x = to_tf32(v.x); v.y = to_tf32(v.y); v.z = to_tf32(v.z); v.w = to_tf32(v.w);
        ((float4*)dst)[i] = v;
    }
}

// ================= pipelined tf32 GEMM (measured-best: 128x256x32, 3 stages) =================
#define GT_BM 128
#define GT_BN 256
#define GT_BK 32
#define A_ST  36
#define B_ST  264
#define ST_AF (GT_BM * A_ST)
#define ST_BF (GT_BK * B_ST)
#define ST_F  (ST_AF + ST_BF)
#define NSTAGE 3
#define GEMM_SMEM (ST_F * NSTAGE * 4)   // 156672 B

__global__ __launch_bounds__(256, 1)
void gemm_tf32_pipe(const float* __restrict__ A, const float* __restrict__ Bw,
                    float* __restrict__ C, int M, int N, int K) {
    extern __shared__ float sm[];
    const uint32_t base = smem_u32(sm);

    const int tid  = threadIdx.x;
    const int warp = tid >> 5, lane = tid & 31;
    const int gid  = lane >> 2, tid4 = lane & 3;
    const int bm   = blockIdx.y * GT_BM, bn = blockIdx.x * GT_BN;
    const int wm   = (warp >> 2) * 64;
    const int wn   = (warp & 3) * 64;

    const int am = tid >> 3, ac = tid & 7;
    const int bk = tid >> 6, bc = tid & 63;
    const int bcol = bn + bc * 4;
    const int bvsz = (bcol + 4 <= N) ? 16 : 0;

    float acc[4][8][4];
#pragma unroll
    for (int mt = 0; mt < 4; mt++)
#pragma unroll
        for (int nt = 0; nt < 8; nt++)
#pragma unroll
            for (int i = 0; i < 4; i++) acc[mt][nt][i] = 0.f;

#define PIPE_LOAD(T)                                                            \
    do {                                                                        \
        const uint32_t _sb = base + (uint32_t)((T) % NSTAGE) * ST_F * 4;        \
        const int _k0 = (T) * GT_BK;                                            \
        _Pragma("unroll")                                                       \
        for (int p = 0; p < 4; p++) {                                           \
            const int m = am + 32 * p;                                          \
            cp16(_sb + (uint32_t)(m * A_ST + ac * 4) * 4,                       \
                 A + (size_t)(bm + m) * K + _k0 + ac * 4);                      \
        }                                                                       \
        _Pragma("unroll")                                                       \
        for (int p = 0; p < 8; p++) {                                           \
            const int kk = bk + 4 * p;                                          \
            cp16z(_sb + (uint32_t)(ST_AF + kk * B_ST + bc * 4) * 4,             \
                  Bw + (size_t)(_k0 + kk) * N + bcol, bvsz);                    \
        }                                                                       \
    } while (0)

    const int nit = K >> 5;
    PIPE_LOAD(0); CP_COMMIT();
    PIPE_LOAD(1); CP_COMMIT();

    for (int t = 0; t < nit; t++) {
        CP_WAIT1();
        __syncthreads();

        const float* Asb = sm + (t % NSTAGE) * ST_F;
        const float* Bsb = Asb + ST_AF;
#pragma unroll
        for (int ks = 0; ks < GT_BK; ks += 8) {
            uint32_t af[4][4];
#pragma unroll
            for (int mt = 0; mt < 4; mt++) {
                const int m0 = wm + mt * 16 + gid;
                af[mt][0] = __float_as_uint(Asb[(m0)     * A_ST + ks + tid4]);
                af[mt][1] = __float_as_uint(Asb[(m0 + 8) * A_ST + ks + tid4]);
                af[mt][2] = __float_as_uint(Asb[(m0)     * A_ST + ks + tid4 + 4]);
                af[mt][3] = __float_as_uint(Asb[(m0 + 8) * A_ST + ks + tid4 + 4]);
            }
#pragma unroll
            for (int nt = 0; nt < 8; nt++) {
                uint32_t bf[2];
                const int n0 = wn + nt * 8 + gid;
                bf[0] = __float_as_uint(Bsb[(ks + tid4)     * B_ST + n0]);
                bf[1] = __float_as_uint(Bsb[(ks + tid4 + 4) * B_ST + n0]);
#pragma unroll
                for (int mt = 0; mt < 4; mt++)
                    mma_tf32(acc[mt][nt], af[mt], bf);
            }
        }
        if (t + 2 < nit) PIPE_LOAD(t + 2);
        CP_COMMIT();
    }
#undef PIPE_LOAD

#pragma unroll
    for (int mt = 0; mt < 4; mt++)
#pragma unroll
        for (int nt = 0; nt < 8; nt++) {
            const int r0 = bm + wm + mt * 16 + gid;
            const int c0 = bn + wn + nt * 8 + 2 * tid4;
            if (c0 < N) {
                *(float2*)&C[(size_t)r0 * N + c0] =
                    make_float2(acc[mt][nt][0], acc[mt][nt][1]);
                *(float2*)&C[(size_t)(r0 + 8) * N + c0] =
                    make_float2(acc[mt][nt][2], acc[mt][nt][3]);
            }
        }
}

// ---------------- conv1d + silu: rolling-window ----------------
#define CONV_L 128
__global__ __launch_bounds__(256)
void conv_kernel(const float* __restrict__ conv_w, const float* __restrict__ conv_b) {
    const int b  = blockIdx.z;
    const int c  = blockIdx.y * 256 + threadIdx.x;
    const int l0 = blockIdx.x * CONV_L;
    if (c >= CONV_DIM) return;

    const float4 w   = *(const float4*)&conv_w[c * 4];
    const float bias = conv_b[c];
    const float* src = g_zxbcdt + (size_t)(b * SEQLEN) * D_IN_PROJ + D_INNER + c;

    float x3 = 0.f, x2 = 0.f, x1 = 0.f;
    if (l0 >= 3) {
        x3 = src[(size_t)(l0 - 3) * D_IN_PROJ];
        x2 = src[(size_t)(l0 - 2) * D_IN_PROJ];
        x1 = src[(size_t)(l0 - 1) * D_IN_PROJ];
    }

    for (int l = l0; l < l0 + CONV_L; l += 4) {
        const float c0 = src[(size_t)(l + 0) * D_IN_PROJ];
        const float c1 = src[(size_t)(l + 1) * D_IN_PROJ];
        const float c2 = src[(size_t)(l + 2) * D_IN_PROJ];
        const float c3 = src[(size_t)(l + 3) * D_IN_PROJ];

        float out[4];
        {
            float a;
            a = fmaf(x3, w.x, bias); a = fmaf(x2, w.y, a); a = fmaf(x1, w.z, a); a = fmaf(c0, w.w, a);
            out[0] = a / (1.f + expf(-a));
            a = fmaf(x2, w.x, bias); a = fmaf(x1, w.y, a); a = fmaf(c0, w.z, a); a = fmaf(c1, w.w, a);
            out[1] = a / (1.f + expf(-a));
            a = fmaf(x1, w.x, bias); a = fmaf(c0, w.y, a); a = fmaf(c1, w.z, a); a = fmaf(c2, w.w, a);
            out[2] = a / (1.f + expf(-a));
            a = fmaf(c0, w.x, bias); a = fmaf(c1, w.y, a); a = fmaf(c2, w.z, a); a = fmaf(c3, w.w, a);
            out[3] = a / (1.f + expf(-a));
        }

#pragma unroll
        for (int u = 0; u < 4; u++) {
            const int row = b * SEQLEN + l + u;
            if (c < D_INNER)
                g_xh[(size_t)row * D_INNER + c] = out[u];
            else if (c < D_INNER + D_STATE)
                g_Bm[row * D_STATE + (c - D_INNER)] = out[u];
            else
                g_Cm[row * D_STATE + (c - D_INNER - D_STATE)] = out[u];
        }
        x3 = c1; x2 = c2; x1 = c3;
    }
}

// ---------------- dt softplus + dA = exp(dt*A) precompute ----------------
__global__ __launch_bounds__(256)
void dt_kernel(const float* __restrict__ dt_bias, const float* __restrict__ A_log) {
    const int idx = blockIdx.x * 256 + threadIdx.x;
    const int row = idx >> 5;
    const int h   = idx & 31;
    const float v  = g_zxbcdt[(size_t)row * D_IN_PROJ + D_INNER + CONV_DIM + h] + dt_bias[h];
    const float sp = (v > 20.f) ? v : log1pf(expf(v));
    const float dA = expf(sp * (-expf(A_log[h])));
    g_dtA[idx] = make_float2(sp, dA);
}

// ---------------- sequential SSM scan: deep cp.async ring, dA precomputed ----------------
#define SC_RING  32
#define SC_GRP   4
#define SC_NGRP  (SEQLEN / SC_GRP)   // 512
#define SC_INFLT 6

__global__ __launch_bounds__(256)
void scan_kernel(float* __restrict__ yscan) {
    __shared__ __align__(16) float Bs[SC_RING][D_STATE];
    __shared__ __align__(16) float Cs[SC_RING][D_STATE];
    __shared__ __align__(16) float Xs[SC_RING][HEADDIM];
    __shared__ __align__(8)  float2 DAs[SC_RING];

    const int b  = blockIdx.x >> 5;
    const int h  = blockIdx.x & 31;
    const int t  = threadIdx.x;
    const int p  = t >> 2;
    const int nq = t & 3;

    const float*  Bp = g_Bm + (size_t)b * SEQLEN * D_STATE;
    const float*  Cp = g_Cm + (size_t)b * SEQLEN * D_STATE;
    const float*  xp = g_xh + (size_t)b * SEQLEN * D_INNER + h * HEADDIM;
    const float2* dp = g_dtA + (size_t)b * SEQLEN * NHEADS + h;
    float*        yp = yscan + (size_t)b * SEQLEN * D_INNER + h * HEADDIM + p;

    const int pu = t >> 6;
    const int po = t & 63;
    const uint32_t sb = smem_u32(&Bs[0][0]);
    const uint32_t sc = smem_u32(&Cs[0][0]);
    const uint32_t sx = smem_u32(&Xs[0][0]);
    const uint32_t sd = smem_u32(&DAs[0]);

#define ISSUE_GROUP(G)                                                         \
    do {                                                                       \
        const int _s   = (G) * SC_GRP + pu;                                    \
        const int _sl  = _s & (SC_RING - 1);                                   \
        if (po < 16)                                                           \
            cp16(sb + (uint32_t)(_sl * D_STATE + po * 4) * 4,                  \
                 Bp + (size_t)_s * D_STATE + po * 4);                          \
        else if (po < 32)                                                      \
            cp16(sc + (uint32_t)(_sl * D_STATE + (po - 16) * 4) * 4,           \
                 Cp + (size_t)_s * D_STATE + (po - 16) * 4);                   \
        else if (po < 48)                                                      \
            cp16(sx + (uint32_t)(_sl * HEADDIM + (po - 32) * 4) * 4,           \
                 xp + (size_t)_s * D_INNER + (po - 32) * 4);                   \
        else if (po == 48)                                                     \
            cp8(sd + (uint32_t)_sl * 8, dp + (size_t)_s * NHEADS);             \
    } while (0)

    unsigned long long hs2[8];
#pragma unroll
    for (int i = 0; i < 8; i++) hs2[i] = 0ull;

#pragma unroll
    for (int g = 0; g < SC_INFLT; g++) { ISSUE_GROUP(g); CP_COMMIT(); }

    for (int g = 0; g < SC_NGRP; g++) {
        CP_WAIT5();
        __syncthreads();

#pragma unroll
        for (int u = 0; u < SC_GRP; u++) {
            const int s  = g * SC_GRP + u;
            const int sl = s & (SC_RING - 1);

            const ulonglong2 b01 = *(const ulonglong2*)&Bs[sl][nq * 16 + 0];
            const ulonglong2 b23 = *(const ulonglong2*)&Bs[sl][nq * 16 + 4];
            const ulonglong2 b45 = *(const ulonglong2*)&Bs[sl][nq * 16 + 8];
            const ulonglong2 b67 = *(const ulonglong2*)&Bs[sl][nq * 16 + 12];
            const ulonglong2 c01 = *(const ulonglong2*)&Cs[sl][nq * 16 + 0];
            const ulonglong2 c23 = *(const ulonglong2*)&Cs[sl][nq * 16 + 4];
            const ulonglong2 c45 = *(const ulonglong2*)&Cs[sl][nq * 16 + 8];
            const ulonglong2 c67 = *(const ulonglong2*)&Cs[sl][nq * 16 + 12];
            const float2 da = DAs[sl];
            const float  xx = Xs[sl][p];

            const float dA  = da.y;
            const float dtx = da.x * xx;
            const unsigned long long dA2  = pack2_(dA, dA);
            const unsigned long long dtx2 = pack2_(dtx, dtx);

            unsigned long long acc2a = 0ull, acc2b = 0ull;
            hs2[0] = fma2_(hs2[0], dA2, mul2_(dtx2, b01.x)); acc2a = fma2_(hs2[0], c01.x, acc2a);
            hs2[1] = fma2_(hs2[1], dA2, mul2_(dtx2, b01.y)); acc2b = fma2_(hs2[1], c01.y, acc2b);
            hs2[2] = fma2_(hs2[2], dA2, mul2_(dtx2, b23.x)); acc2a = fma2_(hs2[2], c23.x, acc2a);
            hs2[3] = fma2_(hs2[3], dA2, mul2_(dtx2, b23.y)); acc2b = fma2_(hs2[3], c23.y, acc2b);
            hs2[4] = fma2_(hs2[4], dA2, mul2_(dtx2, b45.x)); acc2a = fma2_(hs2[4], c45.x, acc2a);
            hs2[5] = fma2_(hs2[5], dA2, mul2_(dtx2, b45.y)); acc2b = fma2_(hs2[5], c45.y, acc2b);
            hs2[6] = fma2_(hs2[6], dA2, mul2_(dtx2, b67.x)); acc2a = fma2_(hs2[6], c67.x, acc2a);
            hs2[7] = fma2_(hs2[7], dA2, mul2_(dtx2, b67.y)); acc2b = fma2_(hs2[7], c67.y, acc2b);

            const float2 aa = unpack2_(acc2a);
            const float2 ab = unpack2_(acc2b);
            float acc = (aa.x + aa.y) + (ab.x + ab.y);
            acc += __shfl_xor_sync(0xffffffffu, acc, 1);
            acc += __shfl_xor_sync(0xffffffffu, acc, 2);
            if (nq == 0) yp[(size_t)s * D_INNER] = acc;
        }

        if (g + SC_INFLT < SC_NGRP) ISSUE_GROUP(g + SC_INFLT);
        CP_COMMIT();
    }
#undef ISSUE_GROUP
}

// ---------------- gate + RMSNorm (emits tf32-rounded y) ----------------
__global__ __launch_bounds__(256)
void gate_norm_kernel(const float* __restrict__ Dv, const float* __restrict__ norm_w) {
    const int row = blockIdx.x;
    const size_t base = (size_t)row * D_INNER;

    float vals[8];
    float ss = 0.f;
#pragma unroll
    for (int i = 0; i < 8; i++) {
        const int c = threadIdx.x + i * 256;
        const float yv = g_yscan[base + c] + g_xh[base + c] * Dv[c >> 6];
        const float z  = g_zxbcdt[(size_t)row * D_IN_PROJ + c];
        const float y  = yv * (z / (1.f + expf(-z)));
        vals[i] = y;
        ss = fmaf(y, y, ss);
    }
#pragma unroll
    for (int o = 16; o > 0; o >>= 1) ss += __shfl_xor_sync(0xffffffffu, ss, o);
    __shared__ float wsum[8];
    if ((threadIdx.x & 31) == 0) wsum[threadIdx.x >> 5] = ss;
    __syncthreads();
    float tot = 0.f;
#pragma unroll
    for (int w = 0; w < 8; w++) tot += wsum[w];
    const float inv = rsqrtf(tot * (1.f / D_INNER) + 1e-5f);
#pragma unroll
    for (int i = 0; i < 8; i++) {
        const int c = threadIdx.x + i * 256;
        g_y[base + c] = to_tf32(vals[i] * inv * norm_w[c]);
    }
}

// ---------------- launch ----------------
extern "C" void kernel_launch(void* const* d_in, const int* in_sizes, int n_in,
                              void* d_out, int out_size) {
    (void)in_sizes; (void)n_in; (void)out_size;
    const float* x       = (const float*)d_in[0];
    const float* W_in    = (const float*)d_in[1];
    const float* conv_w  = (const float*)d_in[2];
    const float* conv_b  = (const float*)d_in[3];
    const float* dt_bias = (const float*)d_in[4];
    const float* A_log   = (const float*)d_in[5];
    const float* Dv      = (const float*)d_in[6];
    const float* norm_w  = (const float*)d_in[7];
    const float* W_out   = (const float*)d_in[8];
    float* out = (float*)d_out;

    float *zx, *ys, *yv, *xr, *w1r, *w2r;
    cudaGetSymbolAddress((void**)&zx,  g_zxbcdt);
    cudaGetSymbolAddress((void**)&ys,  g_yscan);
    cudaGetSymbolAddress((void**)&yv,  g_y);
    cudaGetSymbolAddress((void**)&xr,  g_xr);
    cudaGetSymbolAddress((void**)&w1r, g_w1r);
    cudaGetSymbolAddress((void**)&w2r, g_w2r);

    cudaFuncSetAttribute(gemm_tf32_pipe, cudaFuncAttributeMaxDynamicSharedMemorySize, GEMM_SMEM);

    // 0) round operands to tf32-in-fp32
    {
        const size_t nx = (size_t)NROWS * D_MODEL / 4;
        round_tf32_kernel<<<(unsigned)((nx + 255) / 256), 256>>>(x, xr, nx);
        const size_t n1 = (size_t)D_MODEL * D_IN_PROJ / 4;
        round_tf32_kernel<<<(unsigned)((n1 + 255) / 256), 256>>>(W_in, w1r, n1);
        const size_t n2 = (size_t)D_INNER * D_MODEL / 4;
        round_tf32_kernel<<<(unsigned)((n2 + 255) / 256), 256>>>(W_out, w2r, n2);
    }

    // 1) zxbcdt = x @ W_in   [8192 x 4256], K=1024
    {
        dim3 g((D_IN_PROJ + GT_BN - 1) / GT_BN, NROWS / GT_BM);
        gemm_tf32_pipe<<<g, 256, GEMM_SMEM>>>(xr, w1r, zx, NROWS, D_IN_PROJ, D_MODEL);
    }

    // 2) conv + silu (rolling window), dt softplus + dA
    {
        dim3 gc(SEQLEN / CONV_L, (CONV_DIM + 255) / 256, BATCH);
        conv_kernel<<<gc, 256>>>(conv_w, conv_b);
        dt_kernel<<<(NROWS * NHEADS) / 256, 256>>>(dt_bias, A_log);
    }

    // 3) SSM scan — LAUNCHED TWICE (idempotent): the dur_us delta vs R15
    //    directly measures the scan's wall time (attribution round).
    scan_kernel<<<BATCH * NHEADS, 256>>>(ys);
    scan_kernel<<<BATCH * NHEADS, 256>>>(ys);

    // 4) gate + RMSNorm
    gate_norm_kernel<<<NROWS, 256>>>(Dv, norm_w);

    // 5) out = y @ W_out   [8192 x 1024], K=2048
    {
        dim3 g(D_MODEL / GT_BN, NROWS / GT_BM);
        gemm_tf32_pipe<<<g, 256, GEMM_SMEM>>>(yv, w2r, out, NROWS, D_MODEL, D_INNER);
    }
}

// round 17
// speedup vs baseline: 1.9081x; 1.9081x over previous
#include <cuda_runtime.h>
#include <math.h>
#include <stdint.h>

// ---------------- problem constants ----------------
#define BATCH    4
#define SEQLEN   2048
#define D_MODEL  1024
#define D_STATE  64
#define D_CONV   4
#define HEADDIM  64
#define D_INNER  2048
#define NHEADS   32
#define CONV_DIM 2176          // D_INNER + 2*D_STATE
#define D_IN_PROJ 4256         // 2*D_INNER + 2*D_STATE + NHEADS
#define NROWS    (BATCH * SEQLEN)   // 8192
#define NBH      (BATCH * NHEADS)   // 128
#define QC       64                  // chunk length
#define NCHUNK   (SEQLEN / QC)       // 32

// ---------------- scratch (static device globals: no allocs allowed) ----------------
__device__ float g_zxbcdt[(size_t)NROWS * D_IN_PROJ];
__device__ float g_xh[(size_t)NROWS * D_INNER];
__device__ float g_Bm[NROWS * D_STATE];
__device__ float g_Cm[NROWS * D_STATE];
__device__ float2 g_dtA[NROWS * NHEADS];                // (dt_softplus, dt*A  [log of dA])
__device__ float g_yscan[(size_t)NROWS * D_INNER];
__device__ float g_y[(size_t)NROWS * D_INNER];
__device__ float g_xr[(size_t)NROWS * D_MODEL];
__device__ float g_w1r[(size_t)D_MODEL * D_IN_PROJ];
__device__ float g_w2r[(size_t)D_INNER * D_MODEL];
// SSD scan scratch
__device__ float g_hS[(size_t)NBH * NCHUNK * HEADDIM * D_STATE];   // chunk-local end states (67MB)
__device__ float g_hin[(size_t)NBH * NCHUNK * HEADDIM * D_STATE];  // chunk input states (67MB)
__device__ float g_P[(size_t)NBH * SEQLEN];                        // within-chunk decay prefix

// ---------------- helpers ----------------
__device__ __forceinline__ float to_tf32(float x) {
    uint32_t u;
    asm("cvt.rna.tf32.f32 %0, %1;" : "=r"(u) : "f"(x));
    return __uint_as_float(u);
}
__device__ __forceinline__ uint32_t smem_u32(const void* p) {
    uint32_t a;
    asm("{ .reg .u64 t; cvta.to.shared.u64 t, %1; cvt.u32.u64 %0, t; }" : "=r"(a) : "l"(p));
    return a;
}
__device__ __forceinline__ void mma_tf32(float* d, const uint32_t* a, const uint32_t* b) {
    asm volatile(
        "mma.sync.aligned.m16n8k8.row.col.f32.tf32.tf32.f32 "
        "{%0,%1,%2,%3}, {%4,%5,%6,%7}, {%8,%9}, {%0,%1,%2,%3};\n"
        : "+f"(d[0]), "+f"(d[1]), "+f"(d[2]), "+f"(d[3])
        : "r"(a[0]), "r"(a[1]), "r"(a[2]), "r"(a[3]), "r"(b[0]), "r"(b[1]));
}
__device__ __forceinline__ void cp16(uint32_t dst, const float* src) {
    asm volatile("cp.async.cg.shared.global [%0], [%1], 16;" :: "r"(dst), "l"(src));
}
__device__ __forceinline__ void cp16z(uint32_t dst, const float* src, int vsz) {
    asm volatile("cp.async.cg.shared.global [%0], [%1], 16, %2;" :: "r"(dst), "l"(src), "r"(vsz));
}
#define CP_COMMIT() asm volatile("cp.async.commit_group;" ::: "memory")
#define CP_WAIT1()  asm volatile("cp.async.wait_group 1;" ::: "memory")

// round fp32 -> tf32-in-fp32
__global__ __launch_bounds__(256)
void round_tf32_kernel(const float* __restrict__ src, float* __restrict__ dst, size_t n4) {
    const size_t i = (size_t)blockIdx.x * 256 + threadIdx.x;
    if (i < n4) {
        float4 v = ((const float4*)src)[i];
        v.x = to_tf32(v.x); v.y = to_tf32(v.y); v.z = to_tf32(v.z); v.w = to_tf32(v.w);
        ((float4*)dst)[i] = v;
    }
}

// ================= pipelined tf32 GEMM (measured-best: 128x256x32, 3 stages) =================
#define GT_BM 128
#define GT_BN 256
#define GT_BK 32
#define A_ST  36
#define B_ST  264
#define ST_AF (GT_BM * A_ST)
#define ST_BF (GT_BK * B_ST)
#define ST_F  (ST_AF + ST_BF)
#define NSTAGE 3
#define GEMM_SMEM (ST_F * NSTAGE * 4)   // 156672 B

__global__ __launch_bounds__(256, 1)
void gemm_tf32_pipe(const float* __restrict__ A, const float* __restrict__ Bw,
                    float* __restrict__ C, int M, int N, int K) {
    extern __shared__ float sm[];
    const uint32_t base = smem_u32(sm);

    const int tid  = threadIdx.x;
    const int warp = tid >> 5, lane = tid & 31;
    const int gid  = lane >> 2, tid4 = lane & 3;
    const int bm   = blockIdx.y * GT_BM, bn = blockIdx.x * GT_BN;
    const int wm   = (warp >> 2) * 64;
    const int wn   = (warp & 3) * 64;

    const int am = tid >> 3, ac = tid & 7;
    const int bk = tid >> 6, bc = tid & 63;
    const int bcol = bn + bc * 4;
    const int bvsz = (bcol + 4 <= N) ? 16 : 0;

    float acc[4][8][4];
#pragma unroll
    for (int mt = 0; mt < 4; mt++)
#pragma unroll
        for (int nt = 0; nt < 8; nt++)
#pragma unroll
            for (int i = 0; i < 4; i++) acc[mt][nt][i] = 0.f;

#define PIPE_LOAD(T)                                                            \
    do {                                                                        \
        const uint32_t _sb = base + (uint32_t)((T) % NSTAGE) * ST_F * 4;        \
        const int _k0 = (T) * GT_BK;                                            \
        _Pragma("unroll")                                                       \
        for (int p = 0; p < 4; p++) {                                           \
            const int m = am + 32 * p;                                          \
            cp16(_sb + (uint32_t)(m * A_ST + ac * 4) * 4,                       \
                 A + (size_t)(bm + m) * K + _k0 + ac * 4);                      \
        }                                                                       \
        _Pragma("unroll")                                                       \
        for (int p = 0; p < 8; p++) {                                           \
            const int kk = bk + 4 * p;                                          \
            cp16z(_sb + (uint32_t)(ST_AF + kk * B_ST + bc * 4) * 4,             \
                  Bw + (size_t)(_k0 + kk) * N + bcol, bvsz);                    \
        }                                                                       \
    } while (0)

    const int nit = K >> 5;
    PIPE_LOAD(0); CP_COMMIT();
    PIPE_LOAD(1); CP_COMMIT();

    for (int t = 0; t < nit; t++) {
        CP_WAIT1();
        __syncthreads();

        const float* Asb = sm + (t % NSTAGE) * ST_F;
        const float* Bsb = Asb + ST_AF;
#pragma unroll
        for (int ks = 0; ks < GT_BK; ks += 8) {
            uint32_t af[4][4];
#pragma unroll
            for (int mt = 0; mt < 4; mt++) {
                const int m0 = wm + mt * 16 + gid;
                af[mt][0] = __float_as_uint(Asb[(m0)     * A_ST + ks + tid4]);
                af[mt][1] = __float_as_uint(Asb[(m0 + 8) * A_ST + ks + tid4]);
                af[mt][2] = __float_as_uint(Asb[(m0)     * A_ST + ks + tid4 + 4]);
                af[mt][3] = __float_as_uint(Asb[(m0 + 8) * A_ST + ks + tid4 + 4]);
            }
#pragma unroll
            for (int nt = 0; nt < 8; nt++) {
                uint32_t bf[2];
                const int n0 = wn + nt * 8 + gid;
                bf[0] = __float_as_uint(Bsb[(ks + tid4)     * B_ST + n0]);
                bf[1] = __float_as_uint(Bsb[(ks + tid4 + 4) * B_ST + n0]);
#pragma unroll
                for (int mt = 0; mt < 4; mt++)
                    mma_tf32(acc[mt][nt], af[mt], bf);
            }
        }
        if (t + 2 < nit) PIPE_LOAD(t + 2);
        CP_COMMIT();
    }
#undef PIPE_LOAD

#pragma unroll
    for (int mt = 0; mt < 4; mt++)
#pragma unroll
        for (int nt = 0; nt < 8; nt++) {
            const int r0 = bm + wm + mt * 16 + gid;
            const int c0 = bn + wn + nt * 8 + 2 * tid4;
            if (c0 < N) {
                *(float2*)&C[(size_t)r0 * N + c0] =
                    make_float2(acc[mt][nt][0], acc[mt][nt][1]);
                *(float2*)&C[(size_t)(r0 + 8) * N + c0] =
                    make_float2(acc[mt][nt][2], acc[mt][nt][3]);
            }
        }
}

// ---------------- conv1d + silu: rolling-window ----------------
#define CONV_L 128
__global__ __launch_bounds__(256)
void conv_kernel(const float* __restrict__ conv_w, const float* __restrict__ conv_b) {
    const int b  = blockIdx.z;
    const int c  = blockIdx.y * 256 + threadIdx.x;
    const int l0 = blockIdx.x * CONV_L;
    if (c >= CONV_DIM) return;

    const float4 w   = *(const float4*)&conv_w[c * 4];
    const float bias = conv_b[c];
    const float* src = g_zxbcdt + (size_t)(b * SEQLEN) * D_IN_PROJ + D_INNER + c;

    float x3 = 0.f, x2 = 0.f, x1 = 0.f;
    if (l0 >= 3) {
        x3 = src[(size_t)(l0 - 3) * D_IN_PROJ];
        x2 = src[(size_t)(l0 - 2) * D_IN_PROJ];
        x1 = src[(size_t)(l0 - 1) * D_IN_PROJ];
    }

    for (int l = l0; l < l0 + CONV_L; l += 4) {
        const float c0 = src[(size_t)(l + 0) * D_IN_PROJ];
        const float c1 = src[(size_t)(l + 1) * D_IN_PROJ];
        const float c2 = src[(size_t)(l + 2) * D_IN_PROJ];
        const float c3 = src[(size_t)(l + 3) * D_IN_PROJ];

        float out[4];
        {
            float a;
            a = fmaf(x3, w.x, bias); a = fmaf(x2, w.y, a); a = fmaf(x1, w.z, a); a = fmaf(c0, w.w, a);
            out[0] = a / (1.f + expf(-a));
            a = fmaf(x2, w.x, bias); a = fmaf(x1, w.y, a); a = fmaf(c0, w.z, a); a = fmaf(c1, w.w, a);
            out[1] = a / (1.f + expf(-a));
            a = fmaf(x1, w.x, bias); a = fmaf(c0, w.y, a); a = fmaf(c1, w.z, a); a = fmaf(c2, w.w, a);
            out[2] = a / (1.f + expf(-a));
            a = fmaf(c0, w.x, bias); a = fmaf(c1, w.y, a); a = fmaf(c2, w.z, a); a = fmaf(c3, w.w, a);
            out[3] = a / (1.f + expf(-a));
        }

#pragma unroll
        for (int u = 0; u < 4; u++) {
            const int row = b * SEQLEN + l + u;
            if (c < D_INNER)
                g_xh[(size_t)row * D_INNER + c] = out[u];
            else if (c < D_INNER + D_STATE)
                g_Bm[row * D_STATE + (c - D_INNER)] = out[u];
            else
                g_Cm[row * D_STATE + (c - D_INNER - D_STATE)] = out[u];
        }
        x3 = c1; x2 = c2; x1 = c3;
    }
}

// ---------------- dt softplus + log-decay (dt*A) ----------------
__global__ __launch_bounds__(256)
void dt_kernel(const float* __restrict__ dt_bias, const float* __restrict__ A_log) {
    const int idx = blockIdx.x * 256 + threadIdx.x;
    const int row = idx >> 5;
    const int h   = idx & 31;
    const float v  = g_zxbcdt[(size_t)row * D_IN_PROJ + D_INNER + CONV_DIM + h] + dt_bias[h];
    const float sp = (v > 20.f) ? v : log1pf(expf(v));
    const float ld = sp * (-expf(A_log[h]));   // log(dA), <= 0
    g_dtA[idx] = make_float2(sp, ld);
}

// ================= SSD chunked scan =================
// Phase A: per (bh, chunk): G = C·B^T ; M = G ∘ L ; Y = M·X~ ; S = (B·diag(E))^T·X~.
// 4096 blocks, 256 threads, three 64x64x64 fp32 GEMMs in smem.
#define PA_ST 68    // smem row stride (floats)
#define PA_SMEM (4 * QC * PA_ST * 4 + 5 * QC * 4)   // Bt,Cs,Xs,Ms + lp,Es,Ps,dts,ldas

__global__ __launch_bounds__(256)
void scan_phaseA(void) {
    extern __shared__ float smA[];
    float* Bt  = smA;                         // [n][s] (transposed)
    float* Cs  = Bt + QC * PA_ST;             // [t][n]
    float* Xs  = Cs + QC * PA_ST;             // [s][p]
    float* Ms  = Xs + QC * PA_ST;             // [t][s]
    float* lp  = Ms + QC * PA_ST;             // cumsum log dA
    float* Es  = lp + QC;                     // exp(lp[63]-lp[s])
    float* Ps  = Es + QC;                     // exp(lp[t])
    float* dts = Ps + QC;
    float* lds = dts + QC;

    const int bh = blockIdx.x >> 5;           // NCHUNK = 32
    const int c  = blockIdx.x & 31;
    const int b  = bh >> 5, h = bh & 31;
    const int tid = threadIdx.x;
    const int s0 = c * QC;

    if (tid < QC) {
        const float2 v = g_dtA[(size_t)(b * SEQLEN + s0 + tid) * NHEADS + h];
        dts[tid] = v.x;
        lds[tid] = v.y;
    }
    __syncthreads();

    // load B (transposed), C, X~ = dt*x
    for (int i = tid; i < QC * QC; i += 256) {
        const int s = i >> 6, n = i & 63;
        const size_t row = (size_t)(b * SEQLEN + s0 + s);
        Bt[n * PA_ST + s] = g_Bm[row * D_STATE + n];
        Cs[s * PA_ST + n] = g_Cm[row * D_STATE + n];
        Xs[s * PA_ST + n] = g_xh[row * D_INNER + h * HEADDIM + n] * dts[s];
    }
    if (tid == 0) {
        float a = 0.f;
        for (int s = 0; s < QC; s++) { a += lds[s]; lp[s] = a; }
    }
    __syncthreads();
    if (tid < QC) {
        Es[tid] = __expf(lp[QC - 1] - lp[tid]);
        Ps[tid] = __expf(lp[tid]);
        g_P[(size_t)bh * SEQLEN + s0 + tid] = Ps[tid];
    }
    __syncthreads();

    const int tr = tid >> 4, sc = tid & 15;
    const int t0 = tr * 4, ss = sc * 4;

    // GEMM1: G[t][s] = sum_n Cs[t][n] * Bt[n][s]; then mask+decay -> Ms
    {
        float g0[4], g1[4], g2[4], g3[4];
#pragma unroll
        for (int j = 0; j < 4; j++) { g0[j] = g1[j] = g2[j] = g3[j] = 0.f; }
        if (t0 + 3 >= ss) {   // not fully masked
            for (int n = 0; n < QC; n++) {
                const float a0 = Cs[(t0 + 0) * PA_ST + n];
                const float a1 = Cs[(t0 + 1) * PA_ST + n];
                const float a2 = Cs[(t0 + 2) * PA_ST + n];
                const float a3 = Cs[(t0 + 3) * PA_ST + n];
                const float4 bv = *(const float4*)&Bt[n * PA_ST + ss];
                const float bj[4] = {bv.x, bv.y, bv.z, bv.w};
#pragma unroll
                for (int j = 0; j < 4; j++) {
                    g0[j] = fmaf(a0, bj[j], g0[j]);
                    g1[j] = fmaf(a1, bj[j], g1[j]);
                    g2[j] = fmaf(a2, bj[j], g2[j]);
                    g3[j] = fmaf(a3, bj[j], g3[j]);
                }
            }
            const float base = lp[ss];
            float pt[4], qs[4];
#pragma unroll
            for (int i = 0; i < 4; i++) pt[i] = __expf(lp[t0 + i] - base);  // t>=ss-3 区: bounded
#pragma unroll
            for (int j = 0; j < 4; j++) qs[j] = __expf(base - lp[ss + j]);  // >=0, small
            float* gr[4] = {g0, g1, g2, g3};
#pragma unroll
            for (int i = 0; i < 4; i++)
#pragma unroll
                for (int j = 0; j < 4; j++) {
                    const float e = (ss + j <= t0 + i) ? pt[i] * qs[j] : 0.f;
                    Ms[(t0 + i) * PA_ST + ss + j] = gr[i][j] * e;
                }
        } else {
#pragma unroll
            for (int i = 0; i < 4; i++)
#pragma unroll
                for (int j = 0; j < 4; j++)
                    Ms[(t0 + i) * PA_ST + ss + j] = 0.f;
        }
    }
    __syncthreads();

    // GEMM2: Y[t][p] = sum_s Ms[t][s] * Xs[s][p]  (p-tile = ss)
    {
        float y0[4], y1[4], y2[4], y3[4];
#pragma unroll
        for (int j = 0; j < 4; j++) { y0[j] = y1[j] = y2[j] = y3[j] = 0.f; }
        for (int s = 0; s < QC; s++) {
            const float a0 = Ms[(t0 + 0) * PA_ST + s];
            const float a1 = Ms[(t0 + 1) * PA_ST + s];
            const float a2 = Ms[(t0 + 2) * PA_ST + s];
            const float a3 = Ms[(t0 + 3) * PA_ST + s];
            const float4 xv = *(const float4*)&Xs[s * PA_ST + ss];
            const float xj[4] = {xv.x, xv.y, xv.z, xv.w};
#pragma unroll
            for (int j = 0; j < 4; j++) {
                y0[j] = fmaf(a0, xj[j], y0[j]);
                y1[j] = fmaf(a1, xj[j], y1[j]);
                y2[j] = fmaf(a2, xj[j], y2[j]);
                y3[j] = fmaf(a3, xj[j], y3[j]);
            }
        }
        float* yr[4] = {y0, y1, y2, y3};
#pragma unroll
        for (int i = 0; i < 4; i++) {
            const size_t row = (size_t)(b * SEQLEN + s0 + t0 + i);
            *(float4*)&g_yscan[row * D_INNER + h * HEADDIM + ss] =
                make_float4(yr[i][0], yr[i][1], yr[i][2], yr[i][3]);
        }
    }

    // GEMM3: S[n][p] = sum_s Bt[n][s]*Es[s] * Xs[s][p]   (n-tile = t0, p-tile = ss)
    {
        float s0a[4], s1a[4], s2a[4], s3a[4];
#pragma unroll
        for (int j = 0; j < 4; j++) { s0a[j] = s1a[j] = s2a[j] = s3a[j] = 0.f; }
        for (int s = 0; s < QC; s++) {
            const float es = Es[s];
            const float a0 = Bt[(t0 + 0) * PA_ST + s] * es;
            const float a1 = Bt[(t0 + 1) * PA_ST + s] * es;
            const float a2 = Bt[(t0 + 2) * PA_ST + s] * es;
            const float a3 = Bt[(t0 + 3) * PA_ST + s] * es;
            const float4 xv = *(const float4*)&Xs[s * PA_ST + ss];
            const float xj[4] = {xv.x, xv.y, xv.z, xv.w};
#pragma unroll
            for (int j = 0; j < 4; j++) {
                s0a[j] = fmaf(a0, xj[j], s0a[j]);
                s1a[j] = fmaf(a1, xj[j], s1a[j]);
                s2a[j] = fmaf(a2, xj[j], s2a[j]);
                s3a[j] = fmaf(a3, xj[j], s3a[j]);
            }
        }
        float* sr[4] = {s0a, s1a, s2a, s3a};
        const size_t basei = (size_t)(bh * NCHUNK + c) * HEADDIM * D_STATE;
#pragma unroll
        for (int i = 0; i < 4; i++)
            *(float4*)&g_hS[basei + (size_t)(t0 + i) * HEADDIM + ss] =
                make_float4(sr[i][0], sr[i][1], sr[i][2], sr[i][3]);
    }
}

// Phase B: per bh, 32-step serial combine: h_in[c+1] = Pend_c*h_in[c] + S_c.
// Stored layout of S/hin: [n][p] (n = state, p = head dim)... S above stored [n][p]
// with n-tile=t0 mapping; consistent since both use same indexing.
__global__ __launch_bounds__(256)
void scan_phaseB(void) {
    const int bh = blockIdx.x;
    const int o  = threadIdx.x * 16;
    float hv[16];
#pragma unroll
    for (int i = 0; i < 16; i++) hv[i] = 0.f;

    for (int c = 0; c < NCHUNK; c++) {
        const size_t basei = (size_t)(bh * NCHUNK + c) * HEADDIM * D_STATE + o;
#pragma unroll
        for (int q = 0; q < 4; q++)
            *(float4*)&g_hin[basei + q * 4] =
                make_float4(hv[q * 4], hv[q * 4 + 1], hv[q * 4 + 2], hv[q * 4 + 3]);
        if (c + 1 < NCHUNK) {
            const float Pend = g_P[(size_t)bh * SEQLEN + c * QC + QC - 1];
#pragma unroll
            for (int q = 0; q < 4; q++) {
                const float4 sv = *(const float4*)&g_hS[basei + q * 4];
                hv[q * 4 + 0] = fmaf(Pend, hv[q * 4 + 0], sv.x);
                hv[q * 4 + 1] = fmaf(Pend, hv[q * 4 + 1], sv.y);
                hv[q * 4 + 2] = fmaf(Pend, hv[q * 4 + 2], sv.z);
                hv[q * 4 + 3] = fmaf(Pend, hv[q * 4 + 3], sv.w);
            }
        }
    }
}

// Phase C: y[t][p] += P_t * sum_n C[t][n] * h_in[n][p]   (chunks 1..31)
__global__ __launch_bounds__(256)
void scan_phaseC(void) {
    __shared__ float Cp[QC * PA_ST];
    __shared__ float Hs[QC * PA_ST];
    __shared__ float Pt[QC];

    const int bh = blockIdx.x / (NCHUNK - 1);
    const int ck = blockIdx.x % (NCHUNK - 1) + 1;
    const int b  = bh >> 5, h = bh & 31;
    const int tid = threadIdx.x;
    const int s0 = ck * QC;

    for (int i = tid; i < QC * QC; i += 256) {
        const int r = i >> 6, n = i & 63;
        Cp[r * PA_ST + n] = g_Cm[(size_t)(b * SEQLEN + s0 + r) * D_STATE + n];
        Hs[r * PA_ST + n] = g_hin[(size_t)(bh * NCHUNK + ck) * HEADDIM * D_STATE + r * HEADDIM + n];
    }
    if (tid < QC) Pt[tid] = g_P[(size_t)bh * SEQLEN + s0 + tid];
    __syncthreads();

    const int tr = tid >> 4, sc = tid & 15;
    const int t0 = tr * 4, p0 = sc * 4;

    float a0[4], a1[4], a2[4], a3[4];
#pragma unroll
    for (int j = 0; j < 4; j++) { a0[j] = a1[j] = a2[j] = a3[j] = 0.f; }
    for (int n = 0; n < QC; n++) {
        const float c0 = Cp[(t0 + 0) * PA_ST + n];
        const float c1 = Cp[(t0 + 1) * PA_ST + n];
        const float c2 = Cp[(t0 + 2) * PA_ST + n];
        const float c3 = Cp[(t0 + 3) * PA_ST + n];
        const float4 hvv = *(const float4*)&Hs[n * PA_ST + p0];
        const float hj[4] = {hvv.x, hvv.y, hvv.z, hvv.w};
#pragma unroll
        for (int j = 0; j < 4; j++) {
            a0[j] = fmaf(c0, hj[j], a0[j]);
            a1[j] = fmaf(c1, hj[j], a1[j]);
            a2[j] = fmaf(c2, hj[j], a2[j]);
            a3[j] = fmaf(c3, hj[j], a3[j]);
        }
    }
    float* ar[4] = {a0, a1, a2, a3};
#pragma unroll
    for (int i = 0; i < 4; i++) {
        const size_t row = (size_t)(b * SEQLEN + s0 + t0 + i);
        float4 y = *(float4*)&g_yscan[row * D_INNER + h * HEADDIM + p0];
        const float pscale = Pt[t0 + i];
        y.x = fmaf(pscale, ar[i][0], y.x);
        y.y = fmaf(pscale, ar[i][1], y.y);
        y.z = fmaf(pscale, ar[i][2], y.z);
        y.w = fmaf(pscale, ar[i][3], y.w);
        *(float4*)&g_yscan[row * D_INNER + h * HEADDIM + p0] = y;
    }
}

// ---------------- gate + RMSNorm (emits tf32-rounded y) ----------------
__global__ __launch_bounds__(256)
void gate_norm_kernel(const float* __restrict__ Dv, const float* __restrict__ norm_w) {
    const int row = blockIdx.x;
    const size_t base = (size_t)row * D_INNER;

    float vals[8];
    float ss = 0.f;
#pragma unroll
    for (int i = 0; i < 8; i++) {
        const int c = threadIdx.x + i * 256;
        const float yv = g_yscan[base + c] + g_xh[base + c] * Dv[c >> 6];
        const float z  = g_zxbcdt[(size_t)row * D_IN_PROJ + c];
        const float y  = yv * (z / (1.f + expf(-z)));
        vals[i] = y;
        ss = fmaf(y, y, ss);
    }
#pragma unroll
    for (int o = 16; o > 0; o >>= 1) ss += __shfl_xor_sync(0xffffffffu, ss, o);
    __shared__ float wsum[8];
    if ((threadIdx.x & 31) == 0) wsum[threadIdx.x >> 5] = ss;
    __syncthreads();
    float tot = 0.f;
#pragma unroll
    for (int w = 0; w < 8; w++) tot += wsum[w];
    const float inv = rsqrtf(tot * (1.f / D_INNER) + 1e-5f);
#pragma unroll
    for (int i = 0; i < 8; i++) {
        const int c = threadIdx.x + i * 256;
        g_y[base + c] = to_tf32(vals[i] * inv * norm_w[c]);
    }
}

// ---------------- launch ----------------
extern "C" void kernel_launch(void* const* d_in, const int* in_sizes, int n_in,
                              void* d_out, int out_size) {
    (void)in_sizes; (void)n_in; (void)out_size;
    const float* x       = (const float*)d_in[0];
    const float* W_in    = (const float*)d_in[1];
    const float* conv_w  = (const float*)d_in[2];
    const float* conv_b  = (const float*)d_in[3];
    const float* dt_bias = (const float*)d_in[4];
    const float* A_log   = (const float*)d_in[5];
    const float* Dv      = (const float*)d_in[6];
    const float* norm_w  = (const float*)d_in[7];
    const float* W_out   = (const float*)d_in[8];
    float* out = (float*)d_out;

    float *zx, *yv, *xr, *w1r, *w2r;
    cudaGetSymbolAddress((void**)&zx,  g_zxbcdt);
    cudaGetSymbolAddress((void**)&yv,  g_y);
    cudaGetSymbolAddress((void**)&xr,  g_xr);
    cudaGetSymbolAddress((void**)&w1r, g_w1r);
    cudaGetSymbolAddress((void**)&w2r, g_w2r);

    cudaFuncSetAttribute(gemm_tf32_pipe, cudaFuncAttributeMaxDynamicSharedMemorySize, GEMM_SMEM);
    cudaFuncSetAttribute(scan_phaseA, cudaFuncAttributeMaxDynamicSharedMemorySize, PA_SMEM);

    // 0) round operands to tf32-in-fp32
    {
        const size_t nx = (size_t)NROWS * D_MODEL / 4;
        round_tf32_kernel<<<(unsigned)((nx + 255) / 256), 256>>>(x, xr, nx);
        const size_t n1 = (size_t)D_MODEL * D_IN_PROJ / 4;
        round_tf32_kernel<<<(unsigned)((n1 + 255) / 256), 256>>>(W_in, w1r, n1);
        const size_t n2 = (size_t)D_INNER * D_MODEL / 4;
        round_tf32_kernel<<<(unsigned)((n2 + 255) / 256), 256>>>(W_out, w2r, n2);
    }

    // 1) zxbcdt = x @ W_in
    {
        dim3 g((D_IN_PROJ + GT_BN - 1) / GT_BN, NROWS / GT_BM);
        gemm_tf32_pipe<<<g, 256, GEMM_SMEM>>>(xr, w1r, zx, NROWS, D_IN_PROJ, D_MODEL);
    }

    // 2) conv + silu, dt softplus + log-decay
    {
        dim3 gc(SEQLEN / CONV_L, (CONV_DIM + 255) / 256, BATCH);
        conv_kernel<<<gc, 256>>>(conv_w, conv_b);
        dt_kernel<<<(NROWS * NHEADS) / 256, 256>>>(dt_bias, A_log);
    }

    // 3) SSD chunked scan
    scan_phaseA<<<NBH * NCHUNK, 256, PA_SMEM>>>();
    scan_phaseB<<<NBH, 256>>>();
    scan_phaseC<<<NBH * (NCHUNK - 1), 256>>>();

    // 4) gate + RMSNorm
    gate_norm_kernel<<<NROWS, 256>>>(Dv, norm_w);

    // 5) out = y @ W_out
    {
        dim3 g(D_MODEL / GT_BN, NROWS / GT_BM);
        gemm_tf32_pipe<<<g, 256, GEMM_SMEM>>>(yv, w2r, out, NROWS, D_MODEL, D_INNER);
    }
}